// round 1
// baseline (speedup 1.0000x reference)
#include <cuda_runtime.h>
#include <cstdint>
#include <cstddef>

// Problem constants
#define S_IN   2048
#define NB     512
#define NSTEPS 2048
#define E_DIM  16
#define T_DIM  32

// ---------------------------------------------------------------------------
// Device scratch (static __device__ arrays; no runtime allocation)
// ---------------------------------------------------------------------------
__device__ float d_hidden[(size_t)NSTEPS * NB * E_DIM];   // 64 MB  h states
__device__ float d_ys[(size_t)NSTEPS * NB * T_DIM];       // 134 MB log-softmax per step
__device__ int   d_ri[NSTEPS];
__device__ int   d_c0[NSTEPS];
__device__ int   d_c1[NSTEPS];
__device__ int   d_inv[S_IN];                             // inv[out_idx[t]] = t
__device__ int   d_order[NSTEPS];                         // nodes sorted by level
__device__ int   d_levOff[NSTEPS + 2];
__device__ int   d_nLevels;
__device__ int   d_is64;
__device__ unsigned d_barCount = 0;
__device__ unsigned d_barGen   = 0;

// ---------------------------------------------------------------------------
// Prep kernel: index-width detection, index conversion, level computation,
// counting sort by level, inverse output permutation. Single block.
// ---------------------------------------------------------------------------
__global__ __launch_bounds__(1024) void prep_kernel(
    const void* __restrict__ xp,
    const void* __restrict__ rip,
    const void* __restrict__ cip,
    const void* __restrict__ oip)
{
    __shared__ int s_c0[NSTEPS];
    __shared__ int s_c1[NSTEPS];
    __shared__ int s_lev[NSTEPS];
    __shared__ int s_cnt[NSTEPS + 1];
    __shared__ int s_flag, s_changed, s_maxlev;

    int tid = threadIdx.x;
    if (tid == 0) { s_flag = 0; s_maxlev = 0; }
    __syncthreads();

    // Detect int64 vs int32: if x is int64 (values < 2^31), every odd int32
    // word is 0. For genuine int32 data the odd words are random in [0,2000).
    {
        const int* xi = (const int*)xp;
        if (xi[2 * tid + 1] != 0) atomicOr(&s_flag, 1);
    }
    __syncthreads();
    int is64 = (s_flag == 0);
    if (tid == 0) d_is64 = is64;

    // Load/convert indices
    for (int t = tid; t < NSTEPS; t += 1024) {
        int ri, c0, c1, oi;
        if (is64) {
            ri = (int)((const long long*)rip)[t];
            c0 = (int)((const long long*)cip)[2 * t];
            c1 = (int)((const long long*)cip)[2 * t + 1];
            oi = (int)((const long long*)oip)[t];
        } else {
            ri = ((const int*)rip)[t];
            c0 = ((const int*)cip)[2 * t];
            c1 = ((const int*)cip)[2 * t + 1];
            oi = ((const int*)oip)[t];
        }
        d_ri[t] = ri; d_c0[t] = c0; d_c1[t] = c1;
        s_c0[t] = c0; s_c1[t] = c1;
        d_inv[oi] = t;
        s_lev[t] = 0;
    }
    __syncthreads();

    // Monotone fixpoint: level[t] = 1 + max(level of hidden children), else 0.
    // Converges in <= depth passes (stale reads only delay convergence).
    for (int pass = 0; pass < NSTEPS + 4; pass++) {
        if (tid == 0) s_changed = 0;
        __syncthreads();
        for (int t = tid; t < NSTEPS; t += 1024) {
            int nl = 0;
            int c0 = s_c0[t], c1 = s_c1[t];
            if (c0 >= S_IN) { int l = s_lev[c0 - S_IN] + 1; if (l > nl) nl = l; }
            if (c1 >= S_IN) { int l = s_lev[c1 - S_IN] + 1; if (l > nl) nl = l; }
            if (nl > s_lev[t]) { s_lev[t] = nl; s_changed = 1; }
        }
        __syncthreads();
        int done = (s_changed == 0);
        __syncthreads();
        if (done) break;
    }

    // Counting sort nodes by level
    for (int l = tid; l <= NSTEPS; l += 1024) s_cnt[l] = 0;
    __syncthreads();
    for (int t = tid; t < NSTEPS; t += 1024) {
        atomicAdd(&s_cnt[s_lev[t]], 1);
        atomicMax(&s_maxlev, s_lev[t]);
    }
    __syncthreads();
    if (tid == 0) {
        int ml = s_maxlev;
        int off = 0;
        for (int l = 0; l <= ml; l++) {
            d_levOff[l] = off;
            int c = s_cnt[l];
            s_cnt[l] = off;          // reuse as scatter cursor
            off += c;
        }
        d_levOff[ml + 1] = off;      // == NSTEPS
        d_nLevels = ml + 1;
    }
    __syncthreads();
    for (int t = tid; t < NSTEPS; t += 1024) {
        int pos = atomicAdd(&s_cnt[s_lev[t]], 1);
        d_order[pos] = t;
    }
}

// ---------------------------------------------------------------------------
// Grid barrier (persistent kernel, 1 block/SM residency guaranteed)
// ---------------------------------------------------------------------------
__device__ __forceinline__ void gridBarrier()
{
    __syncthreads();
    if (threadIdx.x == 0) {
        __threadfence();
        unsigned gen = *((volatile unsigned*)&d_barGen);
        unsigned arrived = atomicAdd(&d_barCount, 1u);
        if (arrived == gridDim.x - 1) {
            d_barCount = 0;
            __threadfence();
            *((volatile unsigned*)&d_barGen) = gen + 1;
        } else {
            while (*((volatile unsigned*)&d_barGen) == gen) __nanosleep(64);
        }
    }
    __syncthreads();
}

// Gather one element of a pool row: input slots come from emb[x[b][idx]],
// hidden slots from d_hidden.
__device__ __forceinline__ float gatherv(int idx, int b, int e,
                                         const void* __restrict__ xp,
                                         const float* __restrict__ emb,
                                         int is64)
{
    if (idx < S_IN) {
        int xv = is64 ? (int)((const long long*)xp)[(size_t)b * S_IN + idx]
                      : ((const int*)xp)[b * S_IN + idx];
        return __ldg(&emb[xv * E_DIM + e]);
    }
    return d_hidden[((size_t)(idx - S_IN) * NB + b) * E_DIM + e];
}

// ---------------------------------------------------------------------------
// Main wavefront scan kernel. Warp = (node, 2 batch rows); 16 lanes per batch,
// lane e owns output column e of attn/out GEMVs and tag columns (2e, 2e+1).
// ---------------------------------------------------------------------------
__global__ __launch_bounds__(512, 1) void scan_kernel(
    const void*  __restrict__ xp,
    const float* __restrict__ emb,
    const float* __restrict__ attn_w,
    const float* __restrict__ attn_b,
    const float* __restrict__ out_w,
    const float* __restrict__ out_b,
    const float* __restrict__ tag_w,
    const float* __restrict__ tag_b)
{
    __shared__ float sWt[E_DIM * T_DIM];   // tag_w [k][tt], 2 KB
    for (int i = threadIdx.x; i < E_DIM * T_DIM; i += blockDim.x)
        sWt[i] = tag_w[i];

    const int lane = threadIdx.x & 31;
    const int e    = lane & 15;
    const int half = lane >> 4;
    const int base = half << 4;

    // Per-lane weight columns in registers
    float Wa[16], Wo[48];
#pragma unroll
    for (int k = 0; k < 16; k++) Wa[k] = attn_w[k * E_DIM + e];
#pragma unroll
    for (int k = 0; k < 48; k++) Wo[k] = out_w[k * E_DIM + e];
    const float ab  = attn_b[e];
    const float ob  = out_b[e];
    const float tb0 = tag_b[2 * e];
    const float tb1 = tag_b[2 * e + 1];
    __syncthreads();

    const int warpGlobal = blockIdx.x * (blockDim.x >> 5) + (threadIdx.x >> 5);
    const int nWarps     = gridDim.x * (blockDim.x >> 5);
    const int is64       = d_is64;
    const int nLev       = d_nLevels;

    for (int lev = 0; lev < nLev; lev++) {
        const int start = d_levOff[lev];
        const int cnt   = d_levOff[lev + 1] - start;
        const int tasks = cnt * (NB / 2);      // (node, batch-pair) tasks

        for (int ti = warpGlobal; ti < tasks; ti += nWarps) {
            const int node = d_order[start + (ti >> 8)];
            const int b    = ((ti & 255) << 1) + half;
            const int ri = d_ri[node], c0 = d_c0[node], c1 = d_c1[node];

            const float r  = fmaxf(gatherv(ri, b, e, xp, emb, is64), 0.0f);
            const float v0 = fmaxf(gatherv(c0, b, e, xp, emb, is64), 0.0f);
            const float v1 = fmaxf(gatherv(c1, b, e, xp, emb, is64), 0.0f);

            // attn[e] = sum_k r[k] * attn_w[k][e] + attn_b[e]
            float a0 = ab, a1 = 0.0f;
#pragma unroll
            for (int k = 0; k < 16; k += 2) {
                a0 = fmaf(__shfl_sync(0xffffffffu, r, base + k),     Wa[k],     a0);
                a1 = fmaf(__shfl_sync(0xffffffffu, r, base + k + 1), Wa[k + 1], a1);
            }
            const float attn = a0 + a1;

            const float ap0 = fmaxf(attn * v0, 0.0f);
            const float ap1 = fmaxf(attn * v1, 0.0f);

            // h[e] = relu( [r | ap0 | ap1] . out_w[:, e] + out_b[e] )
            float h0 = ob, h1 = 0.0f, h2 = 0.0f, h3 = 0.0f;
#pragma unroll
            for (int k = 0; k < 16; k += 2) {
                h0 = fmaf(__shfl_sync(0xffffffffu, r,   base + k),     Wo[k],          h0);
                h1 = fmaf(__shfl_sync(0xffffffffu, r,   base + k + 1), Wo[k + 1],      h1);
                h2 = fmaf(__shfl_sync(0xffffffffu, ap0, base + k),     Wo[16 + k],     h2);
                h3 = fmaf(__shfl_sync(0xffffffffu, ap0, base + k + 1), Wo[16 + k + 1], h3);
                h0 = fmaf(__shfl_sync(0xffffffffu, ap1, base + k),     Wo[32 + k],     h0);
                h1 = fmaf(__shfl_sync(0xffffffffu, ap1, base + k + 1), Wo[32 + k + 1], h1);
            }
            const float h = fmaxf(h0 + h1 + h2 + h3, 0.0f);
            d_hidden[((size_t)node * NB + b) * E_DIM + e] = h;

            // logits: lane computes tt = 2e, 2e+1
            float z0 = tb0, z1 = tb1;
#pragma unroll
            for (int k = 0; k < 16; k++) {
                const float hh = __shfl_sync(0xffffffffu, h, base + k);
                const float2 w = *(const float2*)&sWt[k * T_DIM + 2 * e];
                z0 = fmaf(hh, w.x, z0);
                z1 = fmaf(hh, w.y, z1);
            }

            // log-softmax over 32 values held 2-per-lane across a 16-lane group
            float m = fmaxf(z0, z1);
#pragma unroll
            for (int off = 8; off; off >>= 1)
                m = fmaxf(m, __shfl_xor_sync(0xffffffffu, m, off));
            float ssum = __expf(z0 - m) + __expf(z1 - m);
#pragma unroll
            for (int off = 8; off; off >>= 1)
                ssum += __shfl_xor_sync(0xffffffffu, ssum, off);
            const float lse = m + __logf(ssum);

            float2 o2;
            o2.x = z0 - lse;
            o2.y = z1 - lse;
            *(float2*)&d_ys[((size_t)node * NB + b) * T_DIM + 2 * e] = o2;
        }
        gridBarrier();
    }
}

// ---------------------------------------------------------------------------
// Final scatter/transpose: y[b][tt][s] = ys[inv[s]][b][tt]
// Coalesced 128B reads per s, coalesced row writes via padded smem tile.
// ---------------------------------------------------------------------------
__global__ __launch_bounds__(256) void transpose_kernel(float* __restrict__ y)
{
    __shared__ float tile[128][33];
    const int b     = blockIdx.y;
    const int sbase = blockIdx.x * 128;
    const int lane  = threadIdx.x & 31;
    const int w     = threadIdx.x >> 5;

    for (int sl = w; sl < 128; sl += 8) {
        const int t = d_inv[sbase + sl];
        tile[sl][lane] = d_ys[((size_t)t * NB + b) * T_DIM + lane];
    }
    __syncthreads();

    for (int idx = threadIdx.x; idx < T_DIM * 128; idx += 256) {
        const int tt = idx >> 7;
        const int i  = idx & 127;
        y[((size_t)b * T_DIM + tt) * S_IN + sbase + i] = tile[i][tt];
    }
}

// ---------------------------------------------------------------------------
// Launch
// ---------------------------------------------------------------------------
extern "C" void kernel_launch(void* const* d_in, const int* in_sizes, int n_in,
                              void* d_out, int out_size)
{
    (void)in_sizes; (void)n_in; (void)out_size;
    const void*  x       = d_in[0];
    const float* emb     = (const float*)d_in[1];
    const float* attn_w  = (const float*)d_in[2];
    const float* attn_b  = (const float*)d_in[3];
    const float* out_w   = (const float*)d_in[4];
    const float* out_b   = (const float*)d_in[5];
    const float* tag_w   = (const float*)d_in[6];
    const float* tag_b   = (const float*)d_in[7];
    const void*  r_idx   = d_in[8];
    const void*  child   = d_in[9];
    const void*  out_idx = d_in[10];

    prep_kernel<<<1, 1024>>>(x, r_idx, child, out_idx);

    int dev = 0, sm = 148;
    cudaGetDevice(&dev);
    cudaDeviceGetAttribute(&sm, cudaDevAttrMultiProcessorCount, dev);
    int grid = sm < 148 ? sm : 148;
    if (grid < 1) grid = 1;

    scan_kernel<<<grid, 512>>>(x, emb, attn_w, attn_b, out_w, out_b, tag_w, tag_b);

    transpose_kernel<<<dim3(S_IN / 128, NB), 256>>>((float*)d_out);
}

// round 3
// speedup vs baseline: 1.7360x; 1.7360x over previous
#include <cuda_runtime.h>
#include <cstdint>
#include <cstddef>

// Problem constants
#define S_IN   2048
#define NB     512
#define NSTEPS 2048
#define E_DIM  16
#define T_DIM  32

// ---------------------------------------------------------------------------
// Device scratch (static __device__ arrays; no runtime allocation)
// ---------------------------------------------------------------------------
__device__ float d_hidden[(size_t)NSTEPS * NB * E_DIM];   // 64 MB  h states
__device__ float d_ys[(size_t)NSTEPS * NB * T_DIM];       // 134 MB log-softmax per step
__device__ int   d_xT[(size_t)S_IN * NB];                 // 4 MB   xT[s][b] int32
__device__ int   d_ri[NSTEPS];
__device__ int   d_c0[NSTEPS];
__device__ int   d_c1[NSTEPS];
__device__ int   d_inv[S_IN];                             // inv[out_idx[t]] = t
__device__ int   d_order[NSTEPS];                         // nodes sorted by level
__device__ int   d_levOff[NSTEPS + 2];
__device__ int   d_nLevels;
__device__ int   d_is64;
__device__ unsigned d_barCount = 0;
__device__ unsigned d_barGen   = 0;

// ---------------------------------------------------------------------------
// Prep kernel: index-width detection, index conversion, level computation,
// counting sort by level, inverse output permutation. Single block.
// ---------------------------------------------------------------------------
__global__ __launch_bounds__(1024) void prep_kernel(
    const void* __restrict__ xp,
    const void* __restrict__ rip,
    const void* __restrict__ cip,
    const void* __restrict__ oip)
{
    __shared__ int s_c0[NSTEPS];
    __shared__ int s_c1[NSTEPS];
    __shared__ int s_lev[NSTEPS];
    __shared__ int s_cnt[NSTEPS + 1];
    __shared__ int s_flag, s_changed, s_maxlev;

    int tid = threadIdx.x;
    if (tid == 0) { s_flag = 0; s_maxlev = 0; }
    __syncthreads();

    // Detect int64 vs int32: if x is int64 (values < 2^31), every odd int32
    // word is 0. For genuine int32 data the odd words are random in [0,2000).
    {
        const int* xi = (const int*)xp;
        if (xi[2 * tid + 1] != 0) atomicOr(&s_flag, 1);
    }
    __syncthreads();
    int is64 = (s_flag == 0);
    if (tid == 0) d_is64 = is64;

    // Load/convert indices
    for (int t = tid; t < NSTEPS; t += 1024) {
        int ri, c0, c1, oi;
        if (is64) {
            ri = (int)((const long long*)rip)[t];
            c0 = (int)((const long long*)cip)[2 * t];
            c1 = (int)((const long long*)cip)[2 * t + 1];
            oi = (int)((const long long*)oip)[t];
        } else {
            ri = ((const int*)rip)[t];
            c0 = ((const int*)cip)[2 * t];
            c1 = ((const int*)cip)[2 * t + 1];
            oi = ((const int*)oip)[t];
        }
        d_ri[t] = ri; d_c0[t] = c0; d_c1[t] = c1;
        s_c0[t] = c0; s_c1[t] = c1;
        d_inv[oi] = t;
        s_lev[t] = 0;
    }
    __syncthreads();

    // Monotone fixpoint: level[t] = 1 + max(level of hidden children), else 0.
    for (int pass = 0; pass < NSTEPS + 4; pass++) {
        if (tid == 0) s_changed = 0;
        __syncthreads();
        for (int t = tid; t < NSTEPS; t += 1024) {
            int nl = 0;
            int c0 = s_c0[t], c1 = s_c1[t];
            if (c0 >= S_IN) { int l = s_lev[c0 - S_IN] + 1; if (l > nl) nl = l; }
            if (c1 >= S_IN) { int l = s_lev[c1 - S_IN] + 1; if (l > nl) nl = l; }
            if (nl > s_lev[t]) { s_lev[t] = nl; s_changed = 1; }
        }
        __syncthreads();
        int done = (s_changed == 0);
        __syncthreads();
        if (done) break;
    }

    // Counting sort nodes by level
    for (int l = tid; l <= NSTEPS; l += 1024) s_cnt[l] = 0;
    __syncthreads();
    for (int t = tid; t < NSTEPS; t += 1024) {
        atomicAdd(&s_cnt[s_lev[t]], 1);
        atomicMax(&s_maxlev, s_lev[t]);
    }
    __syncthreads();
    if (tid == 0) {
        int ml = s_maxlev;
        int off = 0;
        for (int l = 0; l <= ml; l++) {
            d_levOff[l] = off;
            int c = s_cnt[l];
            s_cnt[l] = off;          // reuse as scatter cursor
            off += c;
        }
        d_levOff[ml + 1] = off;      // == NSTEPS
        d_nLevels = ml + 1;
    }
    __syncthreads();
    for (int t = tid; t < NSTEPS; t += 1024) {
        int pos = atomicAdd(&s_cnt[s_lev[t]], 1);
        d_order[pos] = t;
    }
}

// ---------------------------------------------------------------------------
// x transpose: xT[s][b] = (int)x[b][s]. Tiled 32x32. Runs after prep (reads
// d_is64).
// ---------------------------------------------------------------------------
__global__ __launch_bounds__(256) void xpose_kernel(const void* __restrict__ xp)
{
    __shared__ int tile[32][33];
    const int is64 = d_is64;
    const int s0 = blockIdx.x * 32;
    const int b0 = blockIdx.y * 32;
    const int tx = threadIdx.x & 31;
    const int ty = threadIdx.x >> 5;   // 0..7

#pragma unroll
    for (int i = ty; i < 32; i += 8) {
        int v;
        if (is64) v = (int)((const long long*)xp)[(size_t)(b0 + i) * S_IN + s0 + tx];
        else      v = ((const int*)xp)[(size_t)(b0 + i) * S_IN + s0 + tx];
        tile[tx][i] = v;               // tile[s_local][b_local]
    }
    __syncthreads();
#pragma unroll
    for (int i = ty; i < 32; i += 8) {
        d_xT[(size_t)(s0 + i) * NB + b0 + tx] = tile[i][tx];
    }
}

// ---------------------------------------------------------------------------
// Grid barrier (persistent kernel, all blocks resident)
// ---------------------------------------------------------------------------
__device__ __forceinline__ void gridBarrier()
{
    __syncthreads();
    if (threadIdx.x == 0) {
        __threadfence();
        unsigned gen = *((volatile unsigned*)&d_barGen);
        unsigned arrived = atomicAdd(&d_barCount, 1u);
        if (arrived == gridDim.x - 1) {
            d_barCount = 0;
            __threadfence();
            *((volatile unsigned*)&d_barGen) = gen + 1;
        } else {
            while (*((volatile unsigned*)&d_barGen) == gen) __nanosleep(32);
        }
    }
    __syncthreads();
}

// Load one pool row (16 floats), relu'd, into v[16].
__device__ __forceinline__ void loadVec(int idx, int b,
                                        const float* __restrict__ emb,
                                        float* v)
{
    const float4* p;
    if (idx < S_IN) {
        int xv = __ldg(&d_xT[(size_t)idx * NB + b]);
        p = (const float4*)(emb + (size_t)xv * E_DIM);
    } else {
        p = (const float4*)(d_hidden + ((size_t)(idx - S_IN) * NB + b) * E_DIM);
    }
#pragma unroll
    for (int i = 0; i < 4; i++) {
        float4 q = __ldg(&p[i]);
        v[4 * i + 0] = fmaxf(q.x, 0.0f);
        v[4 * i + 1] = fmaxf(q.y, 0.0f);
        v[4 * i + 2] = fmaxf(q.z, 0.0f);
        v[4 * i + 3] = fmaxf(q.w, 0.0f);
    }
}

// ---------------------------------------------------------------------------
// Main wavefront scan kernel: one THREAD per (node, batch). Full E=16
// pipeline in registers; weights broadcast from smem (no shuffles anywhere).
// ---------------------------------------------------------------------------
__global__ __launch_bounds__(256, 2) void scan_kernel(
    const float* __restrict__ emb,
    const float* __restrict__ attn_w,
    const float* __restrict__ attn_b,
    const float* __restrict__ out_w,
    const float* __restrict__ out_b,
    const float* __restrict__ tag_w,
    const float* __restrict__ tag_b)
{
    __shared__ float sWa[E_DIM * E_DIM];       // attn_w [k][j]    1 KB
    __shared__ float sWo[3 * E_DIM * E_DIM];   // out_w  [k][j]    3 KB
    __shared__ float sWt[E_DIM * T_DIM];       // tag_w  [k][tt]   2 KB
    __shared__ float sAb[E_DIM], sOb[E_DIM], sTb[T_DIM];

    for (int i = threadIdx.x; i < E_DIM * E_DIM; i += blockDim.x) sWa[i] = attn_w[i];
    for (int i = threadIdx.x; i < 3 * E_DIM * E_DIM; i += blockDim.x) sWo[i] = out_w[i];
    for (int i = threadIdx.x; i < E_DIM * T_DIM; i += blockDim.x) sWt[i] = tag_w[i];
    if (threadIdx.x < E_DIM) {
        sAb[threadIdx.x] = attn_b[threadIdx.x];
        sOb[threadIdx.x] = out_b[threadIdx.x];
    }
    if (threadIdx.x < T_DIM) sTb[threadIdx.x] = tag_b[threadIdx.x];
    __syncthreads();

    const int gtid     = blockIdx.x * blockDim.x + threadIdx.x;
    const int nThreads = gridDim.x * blockDim.x;
    const int nLev     = d_nLevels;

    for (int lev = 0; lev < nLev; lev++) {
        const int start = d_levOff[lev];
        const int tasks = (d_levOff[lev + 1] - start) << 9;   // cnt * 512

        for (int t = gtid; t < tasks; t += nThreads) {
            const int node = __ldg(&d_order[start + (t >> 9)]);
            const int b    = t & (NB - 1);
            const int ri = __ldg(&d_ri[node]);
            const int c0 = __ldg(&d_c0[node]);
            const int c1 = __ldg(&d_c1[node]);

            float r[E_DIM], v0[E_DIM], v1[E_DIM];
            loadVec(ri, b, emb, r);
            loadVec(c0, b, emb, v0);
            loadVec(c1, b, emb, v1);

            // attn = r @ attn_w + attn_b
            float a[E_DIM];
#pragma unroll
            for (int j = 0; j < E_DIM; j++) a[j] = sAb[j];
#pragma unroll
            for (int k = 0; k < E_DIM; k++) {
                const float rk = r[k];
#pragma unroll
                for (int j = 0; j < E_DIM; j++)
                    a[j] = fmaf(rk, sWa[k * E_DIM + j], a[j]);
            }

            // applied children: ap = relu(attn * child)   (reuse v0/v1)
#pragma unroll
            for (int j = 0; j < E_DIM; j++) {
                v0[j] = fmaxf(a[j] * v0[j], 0.0f);
                v1[j] = fmaxf(a[j] * v1[j], 0.0f);
            }

            // h = relu([r | ap0 | ap1] @ out_w + out_b)
            float h[E_DIM];
#pragma unroll
            for (int j = 0; j < E_DIM; j++) h[j] = sOb[j];
#pragma unroll
            for (int k = 0; k < E_DIM; k++) {
                const float rk = r[k], p0 = v0[k], p1 = v1[k];
#pragma unroll
                for (int j = 0; j < E_DIM; j++) {
                    h[j] = fmaf(rk, sWo[k * E_DIM + j], h[j]);
                    h[j] = fmaf(p0, sWo[(E_DIM + k) * E_DIM + j], h[j]);
                    h[j] = fmaf(p1, sWo[(2 * E_DIM + k) * E_DIM + j], h[j]);
                }
            }
#pragma unroll
            for (int j = 0; j < E_DIM; j++) h[j] = fmaxf(h[j], 0.0f);

            // write hidden state (64B contiguous per thread)
            {
                float4* hw = (float4*)(d_hidden + ((size_t)node * NB + b) * E_DIM);
#pragma unroll
                for (int i = 0; i < 4; i++)
                    hw[i] = make_float4(h[4 * i], h[4 * i + 1], h[4 * i + 2], h[4 * i + 3]);
            }

            // logits z = h @ tag_w + tag_b, then log-softmax (thread-local)
            float z[T_DIM];
#pragma unroll
            for (int j = 0; j < T_DIM; j++) z[j] = sTb[j];
#pragma unroll
            for (int k = 0; k < E_DIM; k++) {
                const float hk = h[k];
#pragma unroll
                for (int j = 0; j < T_DIM; j++)
                    z[j] = fmaf(hk, sWt[k * T_DIM + j], z[j]);
            }

            float m = z[0];
#pragma unroll
            for (int j = 1; j < T_DIM; j++) m = fmaxf(m, z[j]);
            float ssum = 0.0f;
#pragma unroll
            for (int j = 0; j < T_DIM; j++) ssum += __expf(z[j] - m);
            const float lse = m + __logf(ssum);

            float4* yw = (float4*)(d_ys + ((size_t)node * NB + b) * T_DIM);
#pragma unroll
            for (int i = 0; i < 8; i++)
                yw[i] = make_float4(z[4 * i] - lse, z[4 * i + 1] - lse,
                                    z[4 * i + 2] - lse, z[4 * i + 3] - lse);
        }
        gridBarrier();
    }
}

// ---------------------------------------------------------------------------
// Final scatter/transpose: y[b][tt][s] = ys[inv[s]][b][tt]
// ---------------------------------------------------------------------------
__global__ __launch_bounds__(256) void transpose_kernel(float* __restrict__ y)
{
    __shared__ float tile[128][33];
    const int b     = blockIdx.y;
    const int sbase = blockIdx.x * 128;
    const int lane  = threadIdx.x & 31;
    const int w     = threadIdx.x >> 5;

    for (int sl = w; sl < 128; sl += 8) {
        const int t = d_inv[sbase + sl];
        tile[sl][lane] = d_ys[((size_t)t * NB + b) * T_DIM + lane];
    }
    __syncthreads();

    for (int idx = threadIdx.x; idx < T_DIM * 128; idx += 256) {
        const int tt = idx >> 7;
        const int i  = idx & 127;
        y[((size_t)b * T_DIM + tt) * S_IN + sbase + i] = tile[i][tt];
    }
}

// ---------------------------------------------------------------------------
// Launch
// ---------------------------------------------------------------------------
extern "C" void kernel_launch(void* const* d_in, const int* in_sizes, int n_in,
                              void* d_out, int out_size)
{
    (void)in_sizes; (void)n_in; (void)out_size;
    const void*  x       = d_in[0];
    const float* emb     = (const float*)d_in[1];
    const float* attn_w  = (const float*)d_in[2];
    const float* attn_b  = (const float*)d_in[3];
    const float* out_w   = (const float*)d_in[4];
    const float* out_b   = (const float*)d_in[5];
    const float* tag_w   = (const float*)d_in[6];
    const float* tag_b   = (const float*)d_in[7];
    const void*  r_idx   = d_in[8];
    const void*  child   = d_in[9];
    const void*  out_idx = d_in[10];

    prep_kernel<<<1, 1024>>>(x, r_idx, child, out_idx);

    xpose_kernel<<<dim3(S_IN / 32, NB / 32), 256>>>(x);

    int dev = 0, sm = 148;
    cudaGetDevice(&dev);
    cudaDeviceGetAttribute(&sm, cudaDevAttrMultiProcessorCount, dev);
    if (sm < 1) sm = 1;

    scan_kernel<<<2 * sm, 256>>>(emb, attn_w, attn_b, out_w, out_b, tag_w, tag_b);

    transpose_kernel<<<dim3(S_IN / 128, NB), 256>>>((float*)d_out);
}

// round 4
// speedup vs baseline: 2.5744x; 1.4829x over previous
#include <cuda_runtime.h>
#include <cstdint>
#include <cstddef>

// Problem constants
#define S_IN   2048
#define NB     512
#define NSTEPS 2048
#define E_DIM  16
#define T_DIM  32

typedef unsigned long long u64;

// ---------------------------------------------------------------------------
// Packed f32x2 helpers (Blackwell)
// ---------------------------------------------------------------------------
__device__ __forceinline__ u64 pk2(float x) {
    u64 r; asm("mov.b64 %0, {%1, %1};" : "=l"(r) : "f"(x)); return r;
}
__device__ __forceinline__ u64 pkpair(float lo, float hi) {
    u64 r; asm("mov.b64 %0, {%1, %2};" : "=l"(r) : "f"(lo), "f"(hi)); return r;
}
__device__ __forceinline__ void upk(u64 v, float& lo, float& hi) {
    asm("mov.b64 {%0, %1}, %2;" : "=f"(lo), "=f"(hi) : "l"(v));
}
__device__ __forceinline__ void fma2(u64& d, u64 a, u64 b) {
    asm("fma.rn.f32x2 %0, %1, %2, %3;" : "=l"(d) : "l"(a), "l"(b), "l"(d));
}

// ---------------------------------------------------------------------------
// Device scratch
// ---------------------------------------------------------------------------
__device__ float d_hidden[(size_t)NSTEPS * NB * E_DIM];   // 64 MB  h states
__device__ int   d_xT[(size_t)S_IN * NB];                 // 4 MB   xT[s][b]
__device__ int   d_ri[NSTEPS];
__device__ int   d_c0[NSTEPS];
__device__ int   d_c1[NSTEPS];
__device__ int   d_inv[S_IN];                             // inv[out_idx[t]] = t
__device__ int   d_order[NSTEPS];
__device__ int   d_levOff[NSTEPS + 2];
__device__ int   d_nLevels;
__device__ int   d_is64;
__device__ unsigned d_barCount = 0;
__device__ unsigned d_barGen   = 0;

// ---------------------------------------------------------------------------
// Prep kernel (unchanged from R3): index width detect, levels, sort, inverse
// ---------------------------------------------------------------------------
__global__ __launch_bounds__(1024) void prep_kernel(
    const void* __restrict__ xp,
    const void* __restrict__ rip,
    const void* __restrict__ cip,
    const void* __restrict__ oip)
{
    __shared__ int s_c0[NSTEPS];
    __shared__ int s_c1[NSTEPS];
    __shared__ int s_lev[NSTEPS];
    __shared__ int s_cnt[NSTEPS + 1];
    __shared__ int s_flag, s_changed, s_maxlev;

    int tid = threadIdx.x;
    if (tid == 0) { s_flag = 0; s_maxlev = 0; }
    __syncthreads();

    {
        const int* xi = (const int*)xp;
        if (xi[2 * tid + 1] != 0) atomicOr(&s_flag, 1);
    }
    __syncthreads();
    int is64 = (s_flag == 0);
    if (tid == 0) d_is64 = is64;

    for (int t = tid; t < NSTEPS; t += 1024) {
        int ri, c0, c1, oi;
        if (is64) {
            ri = (int)((const long long*)rip)[t];
            c0 = (int)((const long long*)cip)[2 * t];
            c1 = (int)((const long long*)cip)[2 * t + 1];
            oi = (int)((const long long*)oip)[t];
        } else {
            ri = ((const int*)rip)[t];
            c0 = ((const int*)cip)[2 * t];
            c1 = ((const int*)cip)[2 * t + 1];
            oi = ((const int*)oip)[t];
        }
        d_ri[t] = ri; d_c0[t] = c0; d_c1[t] = c1;
        s_c0[t] = c0; s_c1[t] = c1;
        d_inv[oi] = t;
        s_lev[t] = 0;
    }
    __syncthreads();

    for (int pass = 0; pass < NSTEPS + 4; pass++) {
        if (tid == 0) s_changed = 0;
        __syncthreads();
        for (int t = tid; t < NSTEPS; t += 1024) {
            int nl = 0;
            int c0 = s_c0[t], c1 = s_c1[t];
            if (c0 >= S_IN) { int l = s_lev[c0 - S_IN] + 1; if (l > nl) nl = l; }
            if (c1 >= S_IN) { int l = s_lev[c1 - S_IN] + 1; if (l > nl) nl = l; }
            if (nl > s_lev[t]) { s_lev[t] = nl; s_changed = 1; }
        }
        __syncthreads();
        int done = (s_changed == 0);
        __syncthreads();
        if (done) break;
    }

    for (int l = tid; l <= NSTEPS; l += 1024) s_cnt[l] = 0;
    __syncthreads();
    for (int t = tid; t < NSTEPS; t += 1024) {
        atomicAdd(&s_cnt[s_lev[t]], 1);
        atomicMax(&s_maxlev, s_lev[t]);
    }
    __syncthreads();
    if (tid == 0) {
        int ml = s_maxlev;
        int off = 0;
        for (int l = 0; l <= ml; l++) {
            d_levOff[l] = off;
            int c = s_cnt[l];
            s_cnt[l] = off;
            off += c;
        }
        d_levOff[ml + 1] = off;
        d_nLevels = ml + 1;
    }
    __syncthreads();
    for (int t = tid; t < NSTEPS; t += 1024) {
        int pos = atomicAdd(&s_cnt[s_lev[t]], 1);
        d_order[pos] = t;
    }
}

// ---------------------------------------------------------------------------
// x transpose: xT[s][b] = (int)x[b][s]
// ---------------------------------------------------------------------------
__global__ __launch_bounds__(256) void xpose_kernel(const void* __restrict__ xp)
{
    __shared__ int tile[32][33];
    const int is64 = d_is64;
    const int s0 = blockIdx.x * 32;
    const int b0 = blockIdx.y * 32;
    const int tx = threadIdx.x & 31;
    const int ty = threadIdx.x >> 5;

#pragma unroll
    for (int i = ty; i < 32; i += 8) {
        int v;
        if (is64) v = (int)((const long long*)xp)[(size_t)(b0 + i) * S_IN + s0 + tx];
        else      v = ((const int*)xp)[(size_t)(b0 + i) * S_IN + s0 + tx];
        tile[tx][i] = v;
    }
    __syncthreads();
#pragma unroll
    for (int i = ty; i < 32; i += 8) {
        d_xT[(size_t)(s0 + i) * NB + b0 + tx] = tile[i][tx];
    }
}

// ---------------------------------------------------------------------------
// Grid barrier (persistent kernel, all blocks resident)
// ---------------------------------------------------------------------------
__device__ __forceinline__ void gridBarrier()
{
    __syncthreads();
    if (threadIdx.x == 0) {
        __threadfence();
        unsigned gen = *((volatile unsigned*)&d_barGen);
        unsigned arrived = atomicAdd(&d_barCount, 1u);
        if (arrived == gridDim.x - 1) {
            d_barCount = 0;
            __threadfence();
            *((volatile unsigned*)&d_barGen) = gen + 1;
        } else {
            while (*((volatile unsigned*)&d_barGen) == gen) __nanosleep(32);
        }
    }
    __syncthreads();
}

// Load one pool row (16 floats), relu'd
__device__ __forceinline__ void loadVec(int idx, int b,
                                        const float* __restrict__ emb,
                                        float* v)
{
    const float4* p;
    if (idx < S_IN) {
        int xv = __ldg(&d_xT[(size_t)idx * NB + b]);
        p = (const float4*)(emb + (size_t)xv * E_DIM);
    } else {
        p = (const float4*)(d_hidden + ((size_t)(idx - S_IN) * NB + b) * E_DIM);
    }
#pragma unroll
    for (int i = 0; i < 4; i++) {
        float4 q = __ldg(&p[i]);
        v[4 * i + 0] = fmaxf(q.x, 0.0f);
        v[4 * i + 1] = fmaxf(q.y, 0.0f);
        v[4 * i + 2] = fmaxf(q.z, 0.0f);
        v[4 * i + 3] = fmaxf(q.w, 0.0f);
    }
}

// ---------------------------------------------------------------------------
// Phase (a): wavefront scan computing ONLY hidden states h.
// Thread per (node, batch); packed f32x2 FMAs; weights in smem as u64 pairs.
// ---------------------------------------------------------------------------
__global__ __launch_bounds__(256, 2) void scan_kernel(
    const float* __restrict__ emb,
    const float* __restrict__ attn_w,
    const float* __restrict__ attn_b,
    const float* __restrict__ out_w,
    const float* __restrict__ out_b)
{
    __shared__ u64 sWa2[E_DIM * 8];        // attn_w pairs [k][jj]
    __shared__ u64 sWo2[3 * E_DIM * 8];    // out_w  pairs [k][jj]
    __shared__ u64 sAb2[8], sOb2[8];

    for (int i = threadIdx.x; i < E_DIM * 8; i += blockDim.x) {
        float2 w = ((const float2*)attn_w)[i];
        sWa2[i] = pkpair(w.x, w.y);
    }
    for (int i = threadIdx.x; i < 3 * E_DIM * 8; i += blockDim.x) {
        float2 w = ((const float2*)out_w)[i];
        sWo2[i] = pkpair(w.x, w.y);
    }
    if (threadIdx.x < 8) {
        float2 wa = ((const float2*)attn_b)[threadIdx.x];
        float2 wo = ((const float2*)out_b)[threadIdx.x];
        sAb2[threadIdx.x] = pkpair(wa.x, wa.y);
        sOb2[threadIdx.x] = pkpair(wo.x, wo.y);
    }
    __syncthreads();

    const int gtid     = blockIdx.x * blockDim.x + threadIdx.x;
    const int nThreads = gridDim.x * blockDim.x;
    const int nLev     = d_nLevels;

    for (int lev = 0; lev < nLev; lev++) {
        const int start = d_levOff[lev];
        const int tasks = (d_levOff[lev + 1] - start) << 9;

        for (int t = gtid; t < tasks; t += nThreads) {
            const int node = __ldg(&d_order[start + (t >> 9)]);
            const int b    = t & (NB - 1);
            const int ri = __ldg(&d_ri[node]);
            const int c0 = __ldg(&d_c0[node]);
            const int c1 = __ldg(&d_c1[node]);

            float r[E_DIM], v0[E_DIM], v1[E_DIM];
            loadVec(ri, b, emb, r);
            loadVec(c0, b, emb, v0);
            loadVec(c1, b, emb, v1);

            // attn = r @ attn_w + attn_b (packed pairs over output cols)
            u64 a2[8];
#pragma unroll
            for (int jj = 0; jj < 8; jj++) a2[jj] = sAb2[jj];
#pragma unroll
            for (int k = 0; k < E_DIM; k++) {
                const u64 rk = pk2(r[k]);
#pragma unroll
                for (int jj = 0; jj < 8; jj++)
                    fma2(a2[jj], rk, sWa2[k * 8 + jj]);
            }
            float a[E_DIM];
#pragma unroll
            for (int jj = 0; jj < 8; jj++) upk(a2[jj], a[2 * jj], a[2 * jj + 1]);

            // applied children: ap = relu(attn * child)
#pragma unroll
            for (int j = 0; j < E_DIM; j++) {
                v0[j] = fmaxf(a[j] * v0[j], 0.0f);
                v1[j] = fmaxf(a[j] * v1[j], 0.0f);
            }

            // h = relu([r | ap0 | ap1] @ out_w + out_b)
            u64 h2[8];
#pragma unroll
            for (int jj = 0; jj < 8; jj++) h2[jj] = sOb2[jj];
#pragma unroll
            for (int k = 0; k < E_DIM; k++) {
                const u64 rk = pk2(r[k]);
                const u64 p0 = pk2(v0[k]);
                const u64 p1 = pk2(v1[k]);
#pragma unroll
                for (int jj = 0; jj < 8; jj++) {
                    fma2(h2[jj], rk, sWo2[k * 8 + jj]);
                    fma2(h2[jj], p0, sWo2[(E_DIM + k) * 8 + jj]);
                    fma2(h2[jj], p1, sWo2[(2 * E_DIM + k) * 8 + jj]);
                }
            }
            float h[E_DIM];
#pragma unroll
            for (int jj = 0; jj < 8; jj++) upk(h2[jj], h[2 * jj], h[2 * jj + 1]);
#pragma unroll
            for (int j = 0; j < E_DIM; j++) h[j] = fmaxf(h[j], 0.0f);

            float4* hw = (float4*)(d_hidden + ((size_t)node * NB + b) * E_DIM);
#pragma unroll
            for (int i = 0; i < 4; i++)
                hw[i] = make_float4(h[4 * i], h[4 * i + 1], h[4 * i + 2], h[4 * i + 3]);
        }
        gridBarrier();
    }
}

// ---------------------------------------------------------------------------
// Phase (b): emit. For each (s, b): node = inv[s]; z = h @ tag_w + tag_b;
// log-softmax; write y[b][tt][s] directly. Warp lanes own consecutive s,
// so each of the 32 tt-stores is a 128B coalesced store. No intermediates.
// ---------------------------------------------------------------------------
__global__ __launch_bounds__(256) void emit_kernel(
    float* __restrict__ y,
    const float* __restrict__ tag_w,
    const float* __restrict__ tag_b)
{
    __shared__ u64 sWt2[E_DIM * 16];   // tag_w pairs [k][jj]
    __shared__ u64 sTb2[16];

    for (int i = threadIdx.x; i < E_DIM * 16; i += blockDim.x) {
        float2 w = ((const float2*)tag_w)[i];
        sWt2[i] = pkpair(w.x, w.y);
    }
    if (threadIdx.x < 16) {
        float2 w = ((const float2*)tag_b)[threadIdx.x];
        sTb2[threadIdx.x] = pkpair(w.x, w.y);
    }
    __syncthreads();

    const int s = blockIdx.x * 128 + (threadIdx.x & 127);
    const int b = blockIdx.y * 2 + (threadIdx.x >> 7);
    const int node = __ldg(&d_inv[s]);

    // h already relu'd when stored
    float h[E_DIM];
    {
        const float4* p = (const float4*)(d_hidden + ((size_t)node * NB + b) * E_DIM);
#pragma unroll
        for (int i = 0; i < 4; i++) {
            float4 q = __ldg(&p[i]);
            h[4 * i + 0] = q.x; h[4 * i + 1] = q.y;
            h[4 * i + 2] = q.z; h[4 * i + 3] = q.w;
        }
    }

    u64 z2[16];
#pragma unroll
    for (int jj = 0; jj < 16; jj++) z2[jj] = sTb2[jj];
#pragma unroll
    for (int k = 0; k < E_DIM; k++) {
        const u64 hk = pk2(h[k]);
#pragma unroll
        for (int jj = 0; jj < 16; jj++)
            fma2(z2[jj], hk, sWt2[k * 16 + jj]);
    }
    float z[T_DIM];
#pragma unroll
    for (int jj = 0; jj < 16; jj++) upk(z2[jj], z[2 * jj], z[2 * jj + 1]);

    float m = z[0];
#pragma unroll
    for (int j = 1; j < T_DIM; j++) m = fmaxf(m, z[j]);
    float ssum = 0.0f;
#pragma unroll
    for (int j = 0; j < T_DIM; j++) ssum += __expf(z[j] - m);
    const float lse = m + __logf(ssum);

    float* yb = y + (size_t)b * T_DIM * S_IN + s;
#pragma unroll
    for (int tt = 0; tt < T_DIM; tt++)
        yb[(size_t)tt * S_IN] = z[tt] - lse;
}

// ---------------------------------------------------------------------------
// Launch
// ---------------------------------------------------------------------------
extern "C" void kernel_launch(void* const* d_in, const int* in_sizes, int n_in,
                              void* d_out, int out_size)
{
    (void)in_sizes; (void)n_in; (void)out_size;
    const void*  x       = d_in[0];
    const float* emb     = (const float*)d_in[1];
    const float* attn_w  = (const float*)d_in[2];
    const float* attn_b  = (const float*)d_in[3];
    const float* out_w   = (const float*)d_in[4];
    const float* out_b   = (const float*)d_in[5];
    const float* tag_w   = (const float*)d_in[6];
    const float* tag_b   = (const float*)d_in[7];
    const void*  r_idx   = d_in[8];
    const void*  child   = d_in[9];
    const void*  out_idx = d_in[10];

    prep_kernel<<<1, 1024>>>(x, r_idx, child, out_idx);

    xpose_kernel<<<dim3(S_IN / 32, NB / 32), 256>>>(x);

    int dev = 0, sm = 148;
    cudaGetDevice(&dev);
    cudaDeviceGetAttribute(&sm, cudaDevAttrMultiProcessorCount, dev);
    if (sm < 1) sm = 1;

    scan_kernel<<<2 * sm, 256>>>(emb, attn_w, attn_b, out_w, out_b);

    emit_kernel<<<dim3(S_IN / 128, NB / 2), 256>>>((float*)d_out, tag_w, tag_b);
}

// round 5
// speedup vs baseline: 2.8663x; 1.1134x over previous
#include <cuda_runtime.h>
#include <cstdint>
#include <cstddef>

// Problem constants
#define S_IN   2048
#define NB     512
#define NSTEPS 2048
#define E_DIM  16
#define T_DIM  32
#define NCHUNK 16                    // 512 batches / 32 lanes

typedef unsigned long long u64;

// ---------------------------------------------------------------------------
// Packed f32x2 helpers (Blackwell)
// ---------------------------------------------------------------------------
__device__ __forceinline__ u64 pk2(float x) {
    u64 r; asm("mov.b64 %0, {%1, %1};" : "=l"(r) : "f"(x)); return r;
}
__device__ __forceinline__ u64 pkpair(float lo, float hi) {
    u64 r; asm("mov.b64 %0, {%1, %2};" : "=l"(r) : "f"(lo), "f"(hi)); return r;
}
__device__ __forceinline__ void upk(u64 v, float& lo, float& hi) {
    asm("mov.b64 {%0, %1}, %2;" : "=f"(lo), "=f"(hi) : "l"(v));
}
__device__ __forceinline__ void fma2(u64& d, u64 a, u64 b) {
    asm("fma.rn.f32x2 %0, %1, %2, %3;" : "=l"(d) : "l"(a), "l"(b), "l"(d));
}

// ---------------------------------------------------------------------------
// Device scratch
// ---------------------------------------------------------------------------
__device__ float d_hidden[(size_t)NSTEPS * NB * E_DIM];   // 64 MB  h states
__device__ int   d_xT[(size_t)S_IN * NB];                 // 4 MB   xT[s][b]
__device__ int   d_ri[NSTEPS];
__device__ int   d_c0[NSTEPS];
__device__ int   d_c1[NSTEPS];
__device__ int   d_inv[S_IN];                             // inv[out_idx[t]] = t
__device__ int   d_flag[NSTEPS * NCHUNK];                 // per (node, chunk) ready
__device__ int   d_is64;

// ---------------------------------------------------------------------------
// Prep: index-width detection, index conversion, inverse perm, flag clear.
// (Node order 0..NSTEPS-1 is already topological — no level sort needed.)
// ---------------------------------------------------------------------------
__global__ __launch_bounds__(1024) void prep_kernel(
    const void* __restrict__ xp,
    const void* __restrict__ rip,
    const void* __restrict__ cip,
    const void* __restrict__ oip)
{
    __shared__ int s_flag;
    int tid = threadIdx.x;
    if (tid == 0) s_flag = 0;
    __syncthreads();

    // Detect int64 vs int32 x: int64 values < 2^31 -> every odd word is 0.
    {
        const int* xi = (const int*)xp;
        if (xi[2 * tid + 1] != 0) atomicOr(&s_flag, 1);
    }
    __syncthreads();
    int is64 = (s_flag == 0);
    if (tid == 0) d_is64 = is64;

    for (int t = tid; t < NSTEPS; t += 1024) {
        int ri, c0, c1, oi;
        if (is64) {
            ri = (int)((const long long*)rip)[t];
            c0 = (int)((const long long*)cip)[2 * t];
            c1 = (int)((const long long*)cip)[2 * t + 1];
            oi = (int)((const long long*)oip)[t];
        } else {
            ri = ((const int*)rip)[t];
            c0 = ((const int*)cip)[2 * t];
            c1 = ((const int*)cip)[2 * t + 1];
            oi = ((const int*)oip)[t];
        }
        d_ri[t] = ri; d_c0[t] = c0; d_c1[t] = c1;
        d_inv[oi] = t;
    }

    // Clear ready flags (graph replays reuse device state)
    for (int i = tid; i < NSTEPS * NCHUNK; i += 1024) d_flag[i] = 0;
}

// ---------------------------------------------------------------------------
// x transpose: xT[s][b] = (int)x[b][s]
// ---------------------------------------------------------------------------
__global__ __launch_bounds__(256) void xpose_kernel(const void* __restrict__ xp)
{
    __shared__ int tile[32][33];
    const int is64 = d_is64;
    const int s0 = blockIdx.x * 32;
    const int b0 = blockIdx.y * 32;
    const int tx = threadIdx.x & 31;
    const int ty = threadIdx.x >> 5;

#pragma unroll
    for (int i = ty; i < 32; i += 8) {
        int v;
        if (is64) v = (int)((const long long*)xp)[(size_t)(b0 + i) * S_IN + s0 + tx];
        else      v = ((const int*)xp)[(size_t)(b0 + i) * S_IN + s0 + tx];
        tile[tx][i] = v;
    }
    __syncthreads();
#pragma unroll
    for (int i = ty; i < 32; i += 8) {
        d_xT[(size_t)(s0 + i) * NB + b0 + tx] = tile[i][tx];
    }
}

// ---------------------------------------------------------------------------
// Dataflow wait: all lanes poll the (warp-uniform) flag, acquire via fence.
// ---------------------------------------------------------------------------
__device__ __forceinline__ void waitFlag(int i)
{
    volatile int* f = &d_flag[i];
    if (!*f) {
        while (!*f) __nanosleep(64);
    }
    __threadfence();
}

// Load one pool row (16 floats), relu'd
__device__ __forceinline__ void loadVec(int idx, int b,
                                        const float* __restrict__ emb,
                                        float* v)
{
    const float4* p;
    if (idx < S_IN) {
        int xv = __ldg(&d_xT[(size_t)idx * NB + b]);
        p = (const float4*)(emb + (size_t)xv * E_DIM);
    } else {
        p = (const float4*)(d_hidden + ((size_t)(idx - S_IN) * NB + b) * E_DIM);
    }
#pragma unroll
    for (int i = 0; i < 4; i++) {
        float4 q = __ldg(&p[i]);
        v[4 * i + 0] = fmaxf(q.x, 0.0f);
        v[4 * i + 1] = fmaxf(q.y, 0.0f);
        v[4 * i + 2] = fmaxf(q.z, 0.0f);
        v[4 * i + 3] = fmaxf(q.w, 0.0f);
    }
}

// ---------------------------------------------------------------------------
// Scan: persistent dataflow kernel. Warp-task ti = node*16 + chunk covers
// 32 batches (b = chunk*32 + lane). No grid barriers: each task spin-waits
// only on its hidden children's ready flags. Node order is topological, and
// warps process their tasks in increasing ti, so with all blocks resident
// progress is guaranteed (minimal-incomplete-task induction).
// ---------------------------------------------------------------------------
__global__ __launch_bounds__(256, 2) void scan_kernel(
    const float* __restrict__ emb,
    const float* __restrict__ attn_w,
    const float* __restrict__ attn_b,
    const float* __restrict__ out_w,
    const float* __restrict__ out_b)
{
    __shared__ u64 sWa2[E_DIM * 8];        // attn_w pairs [k][jj]
    __shared__ u64 sWo2[3 * E_DIM * 8];    // out_w  pairs [k][jj]
    __shared__ u64 sAb2[8], sOb2[8];

    for (int i = threadIdx.x; i < E_DIM * 8; i += blockDim.x) {
        float2 w = ((const float2*)attn_w)[i];
        sWa2[i] = pkpair(w.x, w.y);
    }
    for (int i = threadIdx.x; i < 3 * E_DIM * 8; i += blockDim.x) {
        float2 w = ((const float2*)out_w)[i];
        sWo2[i] = pkpair(w.x, w.y);
    }
    if (threadIdx.x < 8) {
        float2 wa = ((const float2*)attn_b)[threadIdx.x];
        float2 wo = ((const float2*)out_b)[threadIdx.x];
        sAb2[threadIdx.x] = pkpair(wa.x, wa.y);
        sOb2[threadIdx.x] = pkpair(wo.x, wo.y);
    }
    __syncthreads();

    const int lane  = threadIdx.x & 31;
    const int gwarp = (blockIdx.x * blockDim.x + threadIdx.x) >> 5;
    const int nW    = (gridDim.x * blockDim.x) >> 5;
    const int nTask = NSTEPS * NCHUNK;

    for (int ti = gwarp; ti < nTask; ti += nW) {
        const int node  = ti >> 4;
        const int chunk = ti & (NCHUNK - 1);
        const int b     = (chunk << 5) + lane;

        const int ri = __ldg(&d_ri[node]);
        const int c0 = __ldg(&d_c0[node]);
        const int c1 = __ldg(&d_c1[node]);

        // Wait for hidden children of this batch-chunk (warp-uniform)
        if (c0 >= S_IN) waitFlag((c0 - S_IN) * NCHUNK + chunk);
        if (c1 >= S_IN) waitFlag((c1 - S_IN) * NCHUNK + chunk);
        if (ri >= S_IN) waitFlag((ri - S_IN) * NCHUNK + chunk);  // defensive

        float r[E_DIM], v0[E_DIM], v1[E_DIM];
        loadVec(ri, b, emb, r);
        loadVec(c0, b, emb, v0);
        loadVec(c1, b, emb, v1);

        // attn = r @ attn_w + attn_b
        u64 a2[8];
#pragma unroll
        for (int jj = 0; jj < 8; jj++) a2[jj] = sAb2[jj];
#pragma unroll
        for (int k = 0; k < E_DIM; k++) {
            const u64 rk = pk2(r[k]);
#pragma unroll
            for (int jj = 0; jj < 8; jj++)
                fma2(a2[jj], rk, sWa2[k * 8 + jj]);
        }
        float a[E_DIM];
#pragma unroll
        for (int jj = 0; jj < 8; jj++) upk(a2[jj], a[2 * jj], a[2 * jj + 1]);

        // applied children: ap = relu(attn * child)
#pragma unroll
        for (int j = 0; j < E_DIM; j++) {
            v0[j] = fmaxf(a[j] * v0[j], 0.0f);
            v1[j] = fmaxf(a[j] * v1[j], 0.0f);
        }

        // h = relu([r | ap0 | ap1] @ out_w + out_b)
        u64 h2[8];
#pragma unroll
        for (int jj = 0; jj < 8; jj++) h2[jj] = sOb2[jj];
#pragma unroll
        for (int k = 0; k < E_DIM; k++) {
            const u64 rk = pk2(r[k]);
            const u64 p0 = pk2(v0[k]);
            const u64 p1 = pk2(v1[k]);
#pragma unroll
            for (int jj = 0; jj < 8; jj++) {
                fma2(h2[jj], rk, sWo2[k * 8 + jj]);
                fma2(h2[jj], p0, sWo2[(E_DIM + k) * 8 + jj]);
                fma2(h2[jj], p1, sWo2[(2 * E_DIM + k) * 8 + jj]);
            }
        }
        float h[E_DIM];
#pragma unroll
        for (int jj = 0; jj < 8; jj++) upk(h2[jj], h[2 * jj], h[2 * jj + 1]);
#pragma unroll
        for (int j = 0; j < E_DIM; j++) h[j] = fmaxf(h[j], 0.0f);

        float4* hw = (float4*)(d_hidden + ((size_t)node * NB + b) * E_DIM);
#pragma unroll
        for (int i = 0; i < 4; i++)
            hw[i] = make_float4(h[4 * i], h[4 * i + 1], h[4 * i + 2], h[4 * i + 3]);

        // Publish: all lanes' stores -> fence -> flag
        __syncwarp();
        __threadfence();
        if (lane == 0) *(volatile int*)&d_flag[ti] = 1;
    }
}

// ---------------------------------------------------------------------------
// Emit: for each (s, b): node = inv[s]; z = h @ tag_w + tag_b; log-softmax;
// write y[b][tt][s] directly (lanes own consecutive s -> coalesced stores).
// ---------------------------------------------------------------------------
__global__ __launch_bounds__(256, 4) void emit_kernel(
    float* __restrict__ y,
    const float* __restrict__ tag_w,
    const float* __restrict__ tag_b)
{
    __shared__ u64 sWt2[E_DIM * 16];   // tag_w pairs [k][jj]
    __shared__ u64 sTb2[16];

    for (int i = threadIdx.x; i < E_DIM * 16; i += blockDim.x) {
        float2 w = ((const float2*)tag_w)[i];
        sWt2[i] = pkpair(w.x, w.y);
    }
    if (threadIdx.x < 16) {
        float2 w = ((const float2*)tag_b)[threadIdx.x];
        sTb2[threadIdx.x] = pkpair(w.x, w.y);
    }
    __syncthreads();

    const int s = blockIdx.x * 128 + (threadIdx.x & 127);
    const int b = blockIdx.y * 2 + (threadIdx.x >> 7);
    const int node = __ldg(&d_inv[s]);

    float h[E_DIM];
    {
        const float4* p = (const float4*)(d_hidden + ((size_t)node * NB + b) * E_DIM);
#pragma unroll
        for (int i = 0; i < 4; i++) {
            float4 q = __ldg(&p[i]);
            h[4 * i + 0] = q.x; h[4 * i + 1] = q.y;
            h[4 * i + 2] = q.z; h[4 * i + 3] = q.w;
        }
    }

    u64 z2[16];
#pragma unroll
    for (int jj = 0; jj < 16; jj++) z2[jj] = sTb2[jj];
#pragma unroll
    for (int k = 0; k < E_DIM; k++) {
        const u64 hk = pk2(h[k]);
#pragma unroll
        for (int jj = 0; jj < 16; jj++)
            fma2(z2[jj], hk, sWt2[k * 16 + jj]);
    }
    float z[T_DIM];
#pragma unroll
    for (int jj = 0; jj < 16; jj++) upk(z2[jj], z[2 * jj], z[2 * jj + 1]);

    float m = z[0];
#pragma unroll
    for (int j = 1; j < T_DIM; j++) m = fmaxf(m, z[j]);
    float ssum = 0.0f;
#pragma unroll
    for (int j = 0; j < T_DIM; j++) ssum += __expf(z[j] - m);
    const float lse = m + __logf(ssum);

    float* yb = y + (size_t)b * T_DIM * S_IN + s;
#pragma unroll
    for (int tt = 0; tt < T_DIM; tt++)
        yb[(size_t)tt * S_IN] = z[tt] - lse;
}

// ---------------------------------------------------------------------------
// Launch
// ---------------------------------------------------------------------------
extern "C" void kernel_launch(void* const* d_in, const int* in_sizes, int n_in,
                              void* d_out, int out_size)
{
    (void)in_sizes; (void)n_in; (void)out_size;
    const void*  x       = d_in[0];
    const float* emb     = (const float*)d_in[1];
    const float* attn_w  = (const float*)d_in[2];
    const float* attn_b  = (const float*)d_in[3];
    const float* out_w   = (const float*)d_in[4];
    const float* out_b   = (const float*)d_in[5];
    const float* tag_w   = (const float*)d_in[6];
    const float* tag_b   = (const float*)d_in[7];
    const void*  r_idx   = d_in[8];
    const void*  child   = d_in[9];
    const void*  out_idx = d_in[10];

    prep_kernel<<<1, 1024>>>(x, r_idx, child, out_idx);

    xpose_kernel<<<dim3(S_IN / 32, NB / 32), 256>>>(x);

    int dev = 0, sm = 148;
    cudaGetDevice(&dev);
    cudaDeviceGetAttribute(&sm, cudaDevAttrMultiProcessorCount, dev);
    if (sm < 1) sm = 1;

    // __launch_bounds__(256, 2) guarantees 2 resident blocks/SM -> all
    // scan blocks co-resident, required for dataflow forward progress.
    scan_kernel<<<2 * sm, 256>>>(emb, attn_w, attn_b, out_w, out_b);

    emit_kernel<<<dim3(S_IN / 128, NB / 2), 256>>>((float*)d_out, tag_w, tag_b);
}